// round 7
// baseline (speedup 1.0000x reference)
#include <cuda_runtime.h>
#include <cuda_fp16.h>
#include <cstdint>
#include <math.h>

#define BB   4
#define NQ   384
#define NK   384
#define DQI  256
#define DKI  256
#define DM   64
#define DFF  256
#define DOUT 64
#define KT   64      // k-rows per CTA tile
#define QG   32      // q items per CTA

#define SROW 528     // H / W1 row stride bytes (16B-aligned, 528 % 128 = 16 -> conflict-free)
#define SW2B 144     // W2 row stride bytes
#define W1_SLICE 8448   // 16 rows x 528 B

#define OFF_H   0                      // 64 x 528 = 33792 (X cols 0..127h, h cols 0..255h)
#define OFF_W1  33792                  // 4 x 8448 = 33792
#define OFF_W2  67584                  // 256 x 144 = 36864
#define OFF_AQ  104448                 // 1024
#define OFF_QS  105472                 // 768
#define OFF_B2  106240                 // 256
#define SMEM_BYTES 106496

// ---------------- device scratch ----------------
__device__ float  g_Aq[BB * NQ * DFF];                    // fp32, exact
__device__ __align__(16) __half g_Bk[BB * NK * DFF];      // fp16
__device__ __align__(16) __half g_W1p[8 * 16 * 264];      // 8 slices [16][264] (528 B rows)
__device__ __align__(16) __half g_W2p[256 * 72];          // [256][72] (144 B rows)

// ---------------- helpers ----------------
__device__ __forceinline__ uint32_t smem_u32(const void* p) {
    uint32_t a;
    asm("{ .reg .u64 t; cvta.to.shared.u64 t, %1; cvt.u32.u64 %0, t; }" : "=r"(a) : "l"(p));
    return a;
}
__device__ __forceinline__ void ldsm4(uint32_t* r, uint32_t addr) {
    asm volatile("ldmatrix.sync.aligned.m8n8.x4.shared.b16 {%0,%1,%2,%3}, [%4];"
        : "=r"(r[0]), "=r"(r[1]), "=r"(r[2]), "=r"(r[3]) : "r"(addr));
}
__device__ __forceinline__ void ldsm4t(uint32_t* r, uint32_t addr) {
    asm volatile("ldmatrix.sync.aligned.m8n8.x4.trans.shared.b16 {%0,%1,%2,%3}, [%4];"
        : "=r"(r[0]), "=r"(r[1]), "=r"(r[2]), "=r"(r[3]) : "r"(addr));
}
__device__ __forceinline__ void mma16(float* d, const uint32_t* a, uint32_t b0, uint32_t b1) {
    asm volatile(
        "mma.sync.aligned.m16n8k16.row.col.f32.f16.f16.f32 "
        "{%0,%1,%2,%3}, {%4,%5,%6,%7}, {%8,%9}, {%0,%1,%2,%3};"
        : "+f"(d[0]), "+f"(d[1]), "+f"(d[2]), "+f"(d[3])
        : "r"(a[0]), "r"(a[1]), "r"(a[2]), "r"(a[3]), "r"(b0), "r"(b1));
}

#define CP16(d, s) asm volatile("cp.async.cg.shared.global [%0], [%1], 16;" :: "r"(d), "l"(s))
#define CPCOMMIT() asm volatile("cp.async.commit_group;")
#define CPWAIT(n)  asm volatile("cp.async.wait_group %0;" :: "n"(n))

// ---------------- prep kernels ----------------
__global__ void prep_q(const float* __restrict__ q_inv, const float* __restrict__ Wq,
                       const float* __restrict__ bq, const float* __restrict__ W1,
                       const float* __restrict__ b1) {
    const int bqi = blockIdx.x, tid = threadIdx.x;   // 256 threads
    __shared__ float sq[DQI];
    __shared__ float sm[DM];
    sq[tid] = q_inv[(size_t)bqi * DQI + tid];
    __syncthreads();
    if (tid < DM) {
        float a0 = 0.f, a1 = 0.f, a2 = 0.f, a3 = 0.f;
        #pragma unroll 16
        for (int i = 0; i < DQI; i += 4) {
            a0 += sq[i]     * Wq[(size_t)i * DM + tid];
            a1 += sq[i + 1] * Wq[(size_t)(i + 1) * DM + tid];
            a2 += sq[i + 2] * Wq[(size_t)(i + 2) * DM + tid];
            a3 += sq[i + 3] * Wq[(size_t)(i + 3) * DM + tid];
        }
        sm[tid] = bq[tid] + ((a0 + a1) + (a2 + a3));
    }
    __syncthreads();
    float a0 = 0.f, a1 = 0.f, a2 = 0.f, a3 = 0.f;
    #pragma unroll 16
    for (int m = 0; m < DM; m += 4) {
        a0 += sm[m]     * W1[(size_t)m * DFF + tid];
        a1 += sm[m + 1] * W1[(size_t)(m + 1) * DFF + tid];
        a2 += sm[m + 2] * W1[(size_t)(m + 2) * DFF + tid];
        a3 += sm[m + 3] * W1[(size_t)(m + 3) * DFF + tid];
    }
    g_Aq[(size_t)bqi * DFF + tid] = b1[tid] + ((a0 + a1) + (a2 + a3));
}

__global__ void prep_kb(const float* __restrict__ k_inv, const float* __restrict__ Wk,
                        const float* __restrict__ bk, const float* __restrict__ W1) {
    const int bki = blockIdx.x, tid = threadIdx.x;   // 256 threads
    __shared__ float sk[DKI];
    __shared__ float sm[DM];
    sk[tid] = k_inv[(size_t)bki * DKI + tid];
    __syncthreads();
    if (tid < DM) {
        float a0 = 0.f, a1 = 0.f, a2 = 0.f, a3 = 0.f;
        #pragma unroll 16
        for (int i = 0; i < DKI; i += 4) {
            a0 += sk[i]     * Wk[(size_t)i * DM + tid];
            a1 += sk[i + 1] * Wk[(size_t)(i + 1) * DM + tid];
            a2 += sk[i + 2] * Wk[(size_t)(i + 2) * DM + tid];
            a3 += sk[i + 3] * Wk[(size_t)(i + 3) * DM + tid];
        }
        sm[tid] = bk[tid] + ((a0 + a1) + (a2 + a3));
    }
    __syncthreads();
    float a0 = 0.f, a1 = 0.f, a2 = 0.f, a3 = 0.f;
    #pragma unroll 16
    for (int m = 0; m < DM; m += 4) {
        a0 += sm[m]     * W1[(size_t)(64 + m) * DFF + tid];
        a1 += sm[m + 1] * W1[(size_t)(65 + m) * DFF + tid];
        a2 += sm[m + 2] * W1[(size_t)(66 + m) * DFF + tid];
        a3 += sm[m + 3] * W1[(size_t)(67 + m) * DFF + tid];
    }
    g_Bk[(size_t)bki * DFF + tid] = __float2half_rn((a0 + a1) + (a2 + a3));
}

// pack W1[128:256,:] -> fp16 slices [8][16][264]; W2 -> fp16 [256][72]
__global__ void prep_pack(const float* __restrict__ W1, const float* __restrict__ W2) {
    const int gid = blockIdx.x * 256 + threadIdx.x;
    if (gid < 8 * 16 * 264) {
        int s = gid / 4224, r = gid % 4224, k = r / 264, n = r % 264;
        float v = (n < 256) ? W1[(size_t)(128 + s * 16 + k) * DFF + n] : 0.f;
        g_W1p[gid] = __float2half_rn(v);
    } else {
        int h = gid - 8 * 16 * 264;
        if (h < 256 * 72) {
            int k = h / 72, n = h % 72;
            float v = (n < 64) ? W2[(size_t)k * DOUT + n] : 0.f;
            g_W2p[h] = __float2half_rn(v);
        }
    }
}

// ---------------- GEMM1 inner-iteration macros ----------------
#define G1_ISSUE(s) do { \
    const char* _src = (const char*)g_W1p + (s) * W1_SLICE; \
    uint32_t _d = sb + OFF_W1 + ((s) & 3) * W1_SLICE + tid * 16; \
    CP16(_d, _src + tid * 16); \
    CP16(_d + 4096, _src + 4096 + tid * 16); \
    if (tid < 16) CP16(_d + 8192, _src + 8192 + tid * 16); \
    CPCOMMIT(); \
} while (0)

#define G1_COMPUTE(ks) do { \
    const uint32_t _slot = sb + OFF_W1 + ((ks) & 3) * W1_SLICE; \
    uint32_t _a0[4], _a1[4]; \
    ldsm4(_a0, aAddr + (ks) * 32); \
    ldsm4(_a1, aAddr + 16 * SROW + (ks) * 32); \
    _Pragma("unroll") \
    for (int _p = 0; _p < 4; _p++) { \
        uint32_t _bb[4]; \
        ldsm4t(_bb, _slot + lrow * SROW + (n0 + _p * 16 + lsel * 8) * 2); \
        mma16(c1[0][2 * _p],     _a0, _bb[0], _bb[1]); \
        mma16(c1[1][2 * _p],     _a1, _bb[0], _bb[1]); \
        mma16(c1[0][2 * _p + 1], _a0, _bb[2], _bb[3]); \
        mma16(c1[1][2 * _p + 1], _a1, _bb[2], _bb[3]); \
    } \
} while (0)

// ---------------- main persistent kernel: 288 CTAs, 2/SM ----------------
__global__ __launch_bounds__(256, 2)
void pm_main(const float* __restrict__ q_equi, const float* __restrict__ k_equi,
             const float* __restrict__ b2, float* __restrict__ out) {
    extern __shared__ char smem[];
    char* Hb = smem + OFF_H;
    float* Aqs = (float*)(smem + OFF_AQ);
    float* qs  = (float*)(smem + OFF_QS);
    float* b2s = (float*)(smem + OFF_B2);
    const uint32_t sb = smem_u32(smem);

    const int kt = blockIdx.x, qg = blockIdx.y, b = blockIdx.z;
    const int kbase = kt * KT;
    const int tid = threadIdx.x, w = tid >> 5, lane = tid & 31;
    const int g = lane >> 2, t = lane & 3;
    const int lrow = lane & 15, lsel = lane >> 4;

    // ---- CTA prologue: W2 resident (one cp.async group), b2 ----
    {
        const char* src = (const char*)g_W2p;
        #pragma unroll
        for (int pass = 0; pass < 9; pass++) {
            uint32_t off = (uint32_t)(pass * 4096 + tid * 16);
            CP16(sb + OFF_W2 + off, src + off);
        }
        CPCOMMIT();
    }
    if (tid < 64) b2s[tid] = b2[tid];

    const int e = tid & 63, kk0 = tid >> 6;
    const float* kp0 = k_equi + (size_t)(b * NK + kbase) * 192 + e;

    const int m0 = (w >> 2) * 32, n0 = (w & 3) * 64;     // GEMM1 warp tile
    const int m2 = (w >> 1) * 16, n2 = (w & 1) * 32;     // GEMM2 warp tile
    const uint32_t aAddr  = sb + OFF_H + (m0 + lrow) * SROW + lsel * 16;
    const uint32_t a2Addr = sb + OFF_H + (m2 + lrow) * SROW + lsel * 16;

    for (int it = 0; it < QG; ++it) {
        const int q = qg * QG + it, bq = b * NQ + q;

        // ---- item prologue: issue W1 slices 0..2, stage qs/Aq ----
        G1_ISSUE(0); G1_ISSUE(1); G1_ISSUE(2);
        if (tid < 192) qs[tid] = q_equi[(size_t)bq * 192 + tid];
        Aqs[tid] = g_Aq[(size_t)bq * DFF + tid];
        __syncthreads();

        // ---- build X = [dot | dist] fp16 into H rows (cols 0..127) ----
        {
            const float q0 = qs[e], q1 = qs[64 + e], q2 = qs[128 + e];
            const float qn2 = q0 * q0 + q1 * q1 + q2 * q2;
            #pragma unroll 4
            for (int j = 0; j < 16; j++) {
                int kk = kk0 + j * 4;
                const float* kp = kp0 + (size_t)kk * 192;
                float k0 = kp[0], k1 = kp[64], k2 = kp[128];
                float dot = q0 * k0 + q1 * k1 + q2 * k2;
                float kn2 = k0 * k0 + k1 * k1 + k2 * k2;
                float dist = sqrtf(fmaxf(qn2 + kn2 - 2.f * dot, 0.f));
                *(__half*)(Hb + kk * SROW + e * 2)       = __float2half_rn(dot);
                *(__half*)(Hb + kk * SROW + 128 + e * 2) = __float2half_rn(dist);
            }
        }

        // ---- GEMM1: [64x128] @ [128x256], W1 through 4-slot ring ----
        float c1[2][8][4];
        #pragma unroll
        for (int mi = 0; mi < 2; mi++)
            #pragma unroll
            for (int ni = 0; ni < 8; ni++)
                #pragma unroll
                for (int z = 0; z < 4; z++) c1[mi][ni][z] = 0.f;

        #pragma unroll
        for (int ks = 0; ks < 5; ks++) {
            CPWAIT(2);            // slice ks landed (W2 group drains first on item 0)
            __syncthreads();
            G1_ISSUE(ks + 3);
            G1_COMPUTE(ks);
        }
        CPWAIT(2); __syncthreads(); G1_COMPUTE(5);
        CPWAIT(1); __syncthreads(); G1_COMPUTE(6);
        CPWAIT(0); __syncthreads(); G1_COMPUTE(7);
        __syncthreads();   // all X reads done before h overwrites H

        // ---- epilogue 1: h = fp16(silu(D1 + Aq + Bk)) -> H cols 0..255 ----
        #pragma unroll
        for (int mi = 0; mi < 2; mi++) {
            const int r0 = m0 + mi * 16 + g, r1 = r0 + 8;
            const __half2* bk0 = (const __half2*)(g_Bk + (size_t)(b * NK + kbase + r0) * DFF);
            const __half2* bk1 = (const __half2*)(g_Bk + (size_t)(b * NK + kbase + r1) * DFF);
            float2 e0[8], e1[8];
            #pragma unroll
            for (int ni = 0; ni < 8; ni++) {
                int c2i = (n0 >> 1) + 4 * ni + t;
                e0[ni] = __half22float2(bk0[c2i]);
                e1[ni] = __half22float2(bk1[c2i]);
            }
            #pragma unroll
            for (int ni = 0; ni < 8; ni++) {
                int f0 = n0 + 8 * ni + 2 * t;
                float2 aq = *(const float2*)(Aqs + f0);
                float v00 = c1[mi][ni][0] + aq.x + e0[ni].x;
                float v01 = c1[mi][ni][1] + aq.y + e0[ni].y;
                float v10 = c1[mi][ni][2] + aq.x + e1[ni].x;
                float v11 = c1[mi][ni][3] + aq.y + e1[ni].y;
                v00 = v00 / (1.f + __expf(-v00));
                v01 = v01 / (1.f + __expf(-v01));
                v10 = v10 / (1.f + __expf(-v10));
                v11 = v11 / (1.f + __expf(-v11));
                *(__half2*)(Hb + r0 * SROW + f0 * 2) = __floats2half2_rn(v00, v01);
                *(__half2*)(Hb + r1 * SROW + f0 * 2) = __floats2half2_rn(v10, v11);
            }
        }
        __syncthreads();

        // ---- GEMM2: [64x256] @ [256x64], W2 resident, no waits ----
        float c2[4][4];
        #pragma unroll
        for (int ni = 0; ni < 4; ni++)
            #pragma unroll
            for (int z = 0; z < 4; z++) c2[ni][z] = 0.f;

        #pragma unroll 4
        for (int ks = 0; ks < 16; ks++) {
            uint32_t a[4];
            ldsm4(a, a2Addr + ks * 32);
            #pragma unroll
            for (int p = 0; p < 2; p++) {
                uint32_t bb[4];
                ldsm4t(bb, sb + OFF_W2 + (ks * 16 + lrow) * SW2B + (n2 + p * 16 + lsel * 8) * 2);
                mma16(c2[2 * p],     a, bb[0], bb[1]);
                mma16(c2[2 * p + 1], a, bb[2], bb[3]);
            }
        }

        // ---- epilogue 2: + b2 -> out ----
        const size_t obase = ((size_t)bq * NK + kbase) * DOUT;
        #pragma unroll
        for (int ni = 0; ni < 4; ni++) {
            int o = n2 + 8 * ni + 2 * t;
            int r0 = m2 + g, r1 = r0 + 8;
            *(float2*)(out + obase + (size_t)r0 * DOUT + o) =
                make_float2(c2[ni][0] + b2s[o], c2[ni][1] + b2s[o + 1]);
            *(float2*)(out + obase + (size_t)r1 * DOUT + o) =
                make_float2(c2[ni][2] + b2s[o], c2[ni][3] + b2s[o + 1]);
        }
        __syncthreads();   // h reads done before next item's X build / staging
    }
}

// ---------------- launcher ----------------
extern "C" void kernel_launch(void* const* d_in, const int* in_sizes, int n_in,
                              void* d_out, int out_size) {
    const float* q_equi = (const float*)d_in[0];
    const float* q_inv  = (const float*)d_in[1];
    const float* k_equi = (const float*)d_in[2];
    const float* k_inv  = (const float*)d_in[3];
    const float* Wq     = (const float*)d_in[4];
    const float* bq     = (const float*)d_in[5];
    const float* Wk     = (const float*)d_in[6];
    const float* bk     = (const float*)d_in[7];
    const float* W1     = (const float*)d_in[8];
    const float* b1     = (const float*)d_in[9];
    const float* W2     = (const float*)d_in[10];
    const float* b2     = (const float*)d_in[11];
    float* out = (float*)d_out;

    cudaFuncSetAttribute(pm_main, cudaFuncAttributeMaxDynamicSharedMemorySize, SMEM_BYTES);

    prep_q<<<BB * NQ, 256>>>(q_inv, Wq, bq, W1, b1);
    prep_kb<<<BB * NK, 256>>>(k_inv, Wk, bk, W1);
    prep_pack<<<(8 * 16 * 264 + 256 * 72 + 255) / 256, 256>>>(W1, W2);
    pm_main<<<dim3(NK / KT, NQ / QG, BB), 256, SMEM_BYTES>>>(q_equi, k_equi, b2, out);
}